// round 9
// baseline (speedup 1.0000x reference)
#include <cuda_runtime.h>
#include <cuda_bf16.h>
#include <cstdint>

// ContrastiveCosineLoss via signed feature-Gram SYRK on warp-level bf16 MMA.
// Round 9: 512-thread gram CTAs (4 quadrants x 4 k-groups), CHUNK=128,
// 3-stage cp.async, SMEM merge tree; split-K=2 + separate combine kernel.

#define N_SAMPLES 2048
#define D_RED     128
#define D_TOT     1152                 // 18 * 64
#define TILE      64
#define NT        (D_TOT / TILE)       // 18
#define NTILES    (NT * (NT + 1) / 2)  // 171
#define NSPLIT    2
#define KSPLIT    (N_SAMPLES / NSPLIT) // 1024
#define CHUNK     128
#define NCHUNK_S  (KSPLIT / CHUNK)     // 8
#define PITCH     72                   // bf16 per SMEM row (144B: LDSM.T bank-safe)
#define STAGES    3
#define SLABB     (CHUNK * PITCH * 2)  // 18432 B per operand slab
#define GSMEM     (STAGES * 2 * SLABB) // 110592 B dynamic smem

__device__ __align__(4096) __nv_bfloat16 g_Yb[N_SAMPLES * D_TOT];
__device__ __align__(4096) float g_G[NSPLIT * NTILES * TILE * TILE];
__device__ float g_part[NTILES];
__device__ unsigned int g_count;       // zero-init; self-resetting

// ---------------------------------------------------------------------------
__device__ __forceinline__ uint32_t smem_u32(const void* p) {
    uint32_t a;
    asm("{ .reg .u64 t; cvta.to.shared.u64 t, %1; cvt.u32.u64 %0, t; }" : "=r"(a) : "l"(p));
    return a;
}
__device__ __forceinline__ void cp16(uint32_t sdst, const void* g) {
    asm volatile("cp.async.cg.shared.global [%0], [%1], 16;" :: "r"(sdst), "l"(g) : "memory");
}
__device__ __forceinline__ void ldsm_x4_t(uint32_t* r, uint32_t addr) {
    asm volatile("ldmatrix.sync.aligned.m8n8.x4.trans.shared.b16 {%0,%1,%2,%3}, [%4];"
                 : "=r"(r[0]), "=r"(r[1]), "=r"(r[2]), "=r"(r[3]) : "r"(addr));
}
__device__ __forceinline__ void mma_bf16(float* c, const uint32_t* a, uint32_t b0, uint32_t b1) {
    asm volatile(
        "mma.sync.aligned.m16n8k16.row.col.f32.bf16.bf16.f32 "
        "{%0,%1,%2,%3}, {%4,%5,%6,%7}, {%8,%9}, {%0,%1,%2,%3};"
        : "+f"(c[0]), "+f"(c[1]), "+f"(c[2]), "+f"(c[3])
        : "r"(a[0]), "r"(a[1]), "r"(a[2]), "r"(a[3]), "r"(b0), "r"(b1));
}

// ---------------------------------------------------------------------------
// Kernel 1: row-normalize -> bf16 row-major. One warp per sample row, MLP 8.
// ---------------------------------------------------------------------------
__global__ void __launch_bounds__(256) normalize_kernel(const float* __restrict__ red,
                                                        const float* __restrict__ full) {
    int t = threadIdx.x, lane = t & 31, wid = t >> 5;
    int row = blockIdx.x * 8 + wid;

    const float4* f4 = (const float4*)(full + (size_t)row * 1024);
    const float4* r4 = (const float4*)(red  + (size_t)row * D_RED);

    float4 fv[8];
    #pragma unroll
    for (int j = 0; j < 8; j++) fv[j] = f4[lane + 32 * j];
    float4 rv = r4[lane];

    float sf = 0.f;
    #pragma unroll
    for (int j = 0; j < 8; j++)
        sf += fv[j].x * fv[j].x + fv[j].y * fv[j].y + fv[j].z * fv[j].z + fv[j].w * fv[j].w;
    float sr = rv.x * rv.x + rv.y * rv.y + rv.z * rv.z + rv.w * rv.w;

    #pragma unroll
    for (int o = 16; o > 0; o >>= 1) {
        sf += __shfl_xor_sync(0xFFFFFFFFu, sf, o);
        sr += __shfl_xor_sync(0xFFFFFFFFu, sr, o);
    }
    float iff = 1.f / fmaxf(sqrtf(sf), 1e-8f);
    float ir  = 1.f / fmaxf(sqrtf(sr), 1e-8f);

    {
        __nv_bfloat162 h0 = __floats2bfloat162_rn(rv.x * ir, rv.y * ir);
        __nv_bfloat162 h1 = __floats2bfloat162_rn(rv.z * ir, rv.w * ir);
        ((uint2*)(g_Yb + (size_t)row * D_TOT))[lane] =
            make_uint2(*(uint32_t*)&h0, *(uint32_t*)&h1);
    }
    uint2* dst = (uint2*)(g_Yb + (size_t)row * D_TOT + D_RED);
    #pragma unroll
    for (int j = 0; j < 8; j++) {
        __nv_bfloat162 h0 = __floats2bfloat162_rn(fv[j].x * iff, fv[j].y * iff);
        __nv_bfloat162 h1 = __floats2bfloat162_rn(fv[j].z * iff, fv[j].w * iff);
        dst[lane + 32 * j] = make_uint2(*(uint32_t*)&h0, *(uint32_t*)&h1);
    }
}

// ---------------------------------------------------------------------------
// Kernel 2: bf16 warp-MMA partial SYRK (split-K=2). 512 threads = 16 warps:
//   wq = wid & 3  -> 32x32 output quadrant of the 64x64 tile
//   kq = wid >> 2 -> 32-sample k-group within the 128-sample chunk
// k-groups merged via SMEM tree at end; writes partial Gram to g_G.
// ---------------------------------------------------------------------------
__global__ void __launch_bounds__(512, 2) gram_kernel() {
    extern __shared__ __align__(16) char dyn[];
    int t = threadIdx.x, lane = t & 31, wid = t >> 5;

    int blk = blockIdx.x, split = blockIdx.y;
    int a = 0, rem = blk, rl = NT;
    while (rem >= rl) { rem -= rl; a++; rl--; }
    int b2 = a + rem;

    // ---- cp.async addressing: 128 rows x 8 segs(16B) per slab; 512 threads
    //      cover 1024 segs in two strided halves (rows 0-63, 64-127).
    int row0 = t >> 3;             // 0..63
    int seg  = (t & 7) * 8;        // bf16 col of 16B segment
    uint32_t sA0 = smem_u32(dyn) + (uint32_t)(row0 * PITCH + seg) * 2;
    uint32_t sB0 = sA0 + SLABB;
    const uint32_t rowStep = 64 * PITCH * 2;
    const __nv_bfloat16* gA0 = g_Yb + (size_t)(split * KSPLIT + row0) * D_TOT + a * TILE + seg;
    const __nv_bfloat16* gB0 = g_Yb + (size_t)(split * KSPLIT + row0) * D_TOT + b2 * TILE + seg;
    const size_t gRow = (size_t)64 * D_TOT;
    const size_t gChunk = (size_t)CHUNK * D_TOT;

    auto load_chunk = [&](int s, int c) {
        uint32_t so = (uint32_t)(s * 2 * SLABB);
        const __nv_bfloat16* ga = gA0 + c * gChunk;
        const __nv_bfloat16* gb = gB0 + c * gChunk;
        cp16(sA0 + so,           ga);
        cp16(sA0 + so + rowStep, ga + gRow);
        cp16(sB0 + so,           gb);
        cp16(sB0 + so + rowStep, gb + gRow);
    };

    // ---- warp tiling ----
    int wq = wid & 3, kq = wid >> 2;
    int m0 = (wq & 1) * 32;
    int n0 = (wq >> 1) * 32;
    int lrow = (lane & 7) + ((lane >> 4) & 1) * 8;
    int lcol = ((lane >> 3) & 1) * 8;
    uint32_t base = smem_u32(dyn);
    uint32_t aA = base + (uint32_t)((kq * 32 + lrow) * PITCH + m0 + lcol) * 2;
    uint32_t aB = base + SLABB + (uint32_t)((kq * 32 + lrow) * PITCH + n0 + lcol) * 2;
    const uint32_t kStep = 16 * PITCH * 2;

    float acc[2][4][4] = {};

    load_chunk(0, 0);
    asm volatile("cp.async.commit_group;" ::: "memory");
    load_chunk(1, 1);
    asm volatile("cp.async.commit_group;" ::: "memory");

    int s = 0;
    for (int c = 0; c < NCHUNK_S; c++) {
        asm volatile("cp.async.wait_group 1;" ::: "memory");
        __syncthreads();

        if (c + 2 < NCHUNK_S) {
            int s2 = s + 2; if (s2 >= STAGES) s2 -= STAGES;
            load_chunk(s2, c + 2);
        }
        asm volatile("cp.async.commit_group;" ::: "memory");

        uint32_t so = (uint32_t)(s * 2 * SLABB);
        #pragma unroll
        for (int ks = 0; ks < 2; ks++) {
            uint32_t ko = so + ks * kStep;
            uint32_t af[2][4], bf[2][4];
            ldsm_x4_t(af[0], aA + ko);
            ldsm_x4_t(af[1], aA + ko + 32);        // +16 m cols
            ldsm_x4_t(bf[0], aB + ko);
            ldsm_x4_t(bf[1], aB + ko + 32);        // +16 n cols
            #pragma unroll
            for (int mi = 0; mi < 2; mi++) {
                mma_bf16(acc[mi][0], af[mi], bf[0][0], bf[0][2]);
                mma_bf16(acc[mi][1], af[mi], bf[0][1], bf[0][3]);
                mma_bf16(acc[mi][2], af[mi], bf[1][0], bf[1][2]);
                mma_bf16(acc[mi][3], af[mi], bf[1][1], bf[1][3]);
            }
        }
        if (++s >= STAGES) s -= STAGES;
    }

    // ---- merge 4 k-groups via SMEM tree, write partial Gram ----
    __syncthreads();
    float4* M4 = (float4*)dyn;                  // 3 x 16KB regions (fits 110KB)
    int tt = wq * 32 + lane;                    // 0..127 within k-group
    if (kq > 0) {
        #pragma unroll
        for (int mi = 0; mi < 2; mi++)
            #pragma unroll
            for (int ni = 0; ni < 4; ni++)
                M4[(kq - 1) * 1024 + (mi * 4 + ni) * 128 + tt] =
                    make_float4(acc[mi][ni][0], acc[mi][ni][1],
                                acc[mi][ni][2], acc[mi][ni][3]);
    }
    __syncthreads();
    if (kq == 0) {
        float4* G4 = (float4*)g_G + ((size_t)(split * NTILES + blk)) * 1024;
        #pragma unroll
        for (int mi = 0; mi < 2; mi++)
            #pragma unroll
            for (int ni = 0; ni < 4; ni++) {
                int f = mi * 4 + ni;
                float4 v1 = M4[f * 128 + tt];
                float4 v2 = M4[1024 + f * 128 + tt];
                float4 v3 = M4[2048 + f * 128 + tt];
                G4[f * 128 + tt] = make_float4(
                    acc[mi][ni][0] + v1.x + v2.x + v3.x,
                    acc[mi][ni][1] + v1.y + v2.y + v3.y,
                    acc[mi][ni][2] + v1.z + v2.z + v3.z,
                    acc[mi][ni][3] + v1.w + v2.w + v3.w);
            }
    }
}

// ---------------------------------------------------------------------------
// Kernel 3: combine splits, square, signed reduce, fused finalize.
// ---------------------------------------------------------------------------
__global__ void __launch_bounds__(256) combine_kernel(float* __restrict__ out) {
    __shared__ float sred[8];
    __shared__ unsigned int s_last;
    int t = threadIdx.x, lane = t & 31, wid = t >> 5;
    int blk = blockIdx.x;

    int a = 0, rem = blk, rl = NT;
    while (rem >= rl) { rem -= rl; a++; rl--; }
    int b2 = a + rem;

    const float4* G4 = (const float4*)g_G;
    size_t o0 = (size_t)blk * 1024;
    size_t o1 = (size_t)(NTILES + blk) * 1024;

    float sum = 0.f;
    #pragma unroll
    for (int f = 0; f < 4; f++) {
        float4 u = G4[o0 + f * 256 + t];
        float4 v = G4[o1 + f * 256 + t];
        float x = u.x + v.x, y = u.y + v.y, z = u.z + v.z, w = u.w + v.w;
        sum += x * x + y * y + z * z + w * w;
    }
    #pragma unroll
    for (int o = 16; o > 0; o >>= 1)
        sum += __shfl_xor_sync(0xFFFFFFFFu, sum, o);
    if (lane == 0) sred[wid] = sum;
    __syncthreads();
    if (t == 0) {
        float tot = 0.f;
        #pragma unroll
        for (int i = 0; i < 8; i++) tot += sred[i];
        float sp = ((a < 2) != (b2 < 2)) ? -1.f : 1.f;
        float w  = sp * ((a == b2) ? 1.f : 2.f);
        g_part[blk] = w * tot;
        __threadfence();
        s_last = (atomicAdd(&g_count, 1u) == NTILES - 1);
    }
    __syncthreads();

    if (s_last) {
        __threadfence();
        __shared__ float fs[256];
        fs[t] = (t < NTILES) ? g_part[t] : 0.f;
        __syncthreads();
        #pragma unroll
        for (int o = 128; o > 0; o >>= 1) {
            if (t < o) fs[t] += fs[t + o];
            __syncthreads();
        }
        if (t == 0) {
            out[0] = fs[0] / ((float)N_SAMPLES * (float)(N_SAMPLES - 1));
            g_count = 0;
        }
    }
}

// ---------------------------------------------------------------------------
extern "C" void kernel_launch(void* const* d_in, const int* in_sizes, int n_in,
                              void* d_out, int out_size) {
    const float* red;
    const float* full;
    if (in_sizes[0] == N_SAMPLES * D_RED) {
        red  = (const float*)d_in[0];
        full = (const float*)d_in[1];
    } else {
        red  = (const float*)d_in[1];
        full = (const float*)d_in[0];
    }

    static int attr_done = 0;
    if (!attr_done) {
        cudaFuncSetAttribute(gram_kernel, cudaFuncAttributeMaxDynamicSharedMemorySize,
                             GSMEM);
        attr_done = 1;
    }

    normalize_kernel<<<N_SAMPLES / 8, 256>>>(red, full);
    gram_kernel<<<dim3(NTILES, NSPLIT), 512, GSMEM>>>();
    combine_kernel<<<NTILES, 256>>>((float*)d_out);
}

// round 10
// speedup vs baseline: 1.1338x; 1.1338x over previous
#include <cuda_runtime.h>
#include <cuda_bf16.h>
#include <cstdint>

// ContrastiveCosineLoss via signed feature-Gram SYRK on warp-level bf16 MMA.
// Round 10: R8 (best: split-K=4, fused decoupled combine) with
// __launch_bounds__(256,3) to raise residency to 3 CTAs/SM (24 warps/SM).

#define N_SAMPLES 2048
#define D_RED     128
#define D_TOT     1152                 // 18 * 64
#define TILE      64
#define NT        (D_TOT / TILE)       // 18
#define NTILES    (NT * (NT + 1) / 2)  // 171
#define NSPLIT    4
#define KSPLIT    (N_SAMPLES / NSPLIT) // 512
#define CHUNK     64
#define NCHUNK_S  (KSPLIT / CHUNK)     // 8
#define PITCH     72                   // bf16 per SMEM row (144B: LDSM.T bank-safe)
#define STAGES    3
#define SLABB     (CHUNK * PITCH * 2)  // 9216 B per operand slab
#define GSMEM     (STAGES * 2 * SLABB) // 55296 B dynamic smem

__device__ __align__(4096) __nv_bfloat16 g_Yb[N_SAMPLES * D_TOT];
__device__ __align__(4096) float g_G[NSPLIT * NTILES * TILE * TILE];
__device__ float g_part[NTILES];
__device__ unsigned int g_tile_count[NTILES];  // zero-init; self-resetting
__device__ unsigned int g_count;               // zero-init; self-resetting

// ---------------------------------------------------------------------------
__device__ __forceinline__ uint32_t smem_u32(const void* p) {
    uint32_t a;
    asm("{ .reg .u64 t; cvta.to.shared.u64 t, %1; cvt.u32.u64 %0, t; }" : "=r"(a) : "l"(p));
    return a;
}
__device__ __forceinline__ void cp16(uint32_t sdst, const void* g) {
    asm volatile("cp.async.cg.shared.global [%0], [%1], 16;" :: "r"(sdst), "l"(g) : "memory");
}
__device__ __forceinline__ void ldsm_x4_t(uint32_t* r, uint32_t addr) {
    asm volatile("ldmatrix.sync.aligned.m8n8.x4.trans.shared.b16 {%0,%1,%2,%3}, [%4];"
                 : "=r"(r[0]), "=r"(r[1]), "=r"(r[2]), "=r"(r[3]) : "r"(addr));
}
__device__ __forceinline__ void mma_bf16(float* c, const uint32_t* a, uint32_t b0, uint32_t b1) {
    asm volatile(
        "mma.sync.aligned.m16n8k16.row.col.f32.bf16.bf16.f32 "
        "{%0,%1,%2,%3}, {%4,%5,%6,%7}, {%8,%9}, {%0,%1,%2,%3};"
        : "+f"(c[0]), "+f"(c[1]), "+f"(c[2]), "+f"(c[3])
        : "r"(a[0]), "r"(a[1]), "r"(a[2]), "r"(a[3]), "r"(b0), "r"(b1));
}

// ---------------------------------------------------------------------------
// Kernel 1: row-normalize -> bf16 row-major. One warp per sample row, MLP 8.
// ---------------------------------------------------------------------------
__global__ void __launch_bounds__(256) normalize_kernel(const float* __restrict__ red,
                                                        const float* __restrict__ full) {
    int t = threadIdx.x, lane = t & 31, wid = t >> 5;
    int row = blockIdx.x * 8 + wid;

    const float4* f4 = (const float4*)(full + (size_t)row * 1024);
    const float4* r4 = (const float4*)(red  + (size_t)row * D_RED);

    float4 fv[8];
    #pragma unroll
    for (int j = 0; j < 8; j++) fv[j] = f4[lane + 32 * j];
    float4 rv = r4[lane];

    float sf = 0.f;
    #pragma unroll
    for (int j = 0; j < 8; j++)
        sf += fv[j].x * fv[j].x + fv[j].y * fv[j].y + fv[j].z * fv[j].z + fv[j].w * fv[j].w;
    float sr = rv.x * rv.x + rv.y * rv.y + rv.z * rv.z + rv.w * rv.w;

    #pragma unroll
    for (int o = 16; o > 0; o >>= 1) {
        sf += __shfl_xor_sync(0xFFFFFFFFu, sf, o);
        sr += __shfl_xor_sync(0xFFFFFFFFu, sr, o);
    }
    float iff = 1.f / fmaxf(sqrtf(sf), 1e-8f);
    float ir  = 1.f / fmaxf(sqrtf(sr), 1e-8f);

    {
        __nv_bfloat162 h0 = __floats2bfloat162_rn(rv.x * ir, rv.y * ir);
        __nv_bfloat162 h1 = __floats2bfloat162_rn(rv.z * ir, rv.w * ir);
        ((uint2*)(g_Yb + (size_t)row * D_TOT))[lane] =
            make_uint2(*(uint32_t*)&h0, *(uint32_t*)&h1);
    }
    uint2* dst = (uint2*)(g_Yb + (size_t)row * D_TOT + D_RED);
    #pragma unroll
    for (int j = 0; j < 8; j++) {
        __nv_bfloat162 h0 = __floats2bfloat162_rn(fv[j].x * iff, fv[j].y * iff);
        __nv_bfloat162 h1 = __floats2bfloat162_rn(fv[j].z * iff, fv[j].w * iff);
        dst[lane + 32 * j] = make_uint2(*(uint32_t*)&h0, *(uint32_t*)&h1);
    }
}

// ---------------------------------------------------------------------------
// Kernel 2: bf16 warp-MMA partial SYRK (split-K=4) + decoupled per-tile
// combine + global finalize. grid = (NTILES, NSPLIT), 256 threads.
// ---------------------------------------------------------------------------
__global__ void __launch_bounds__(256, 3) gram_kernel(float* __restrict__ out) {
    extern __shared__ __align__(16) char dyn[];
    __shared__ float sred[8];
    __shared__ unsigned int s_comb, s_last;

    int t = threadIdx.x, lane = t & 31, wid = t >> 5;

    int blk = blockIdx.x, split = blockIdx.y;
    int a = 0, rem = blk, rl = NT;
    while (rem >= rl) { rem -= rl; a++; rl--; }
    int b2 = a + rem;

    // ---- hoisted cp.async addressing ----
    int lrowg = t >> 3;
    int lv    = (t & 7) * 8;
    uint32_t sA0 = smem_u32(dyn) + (uint32_t)(lrowg * PITCH + lv) * 2;
    uint32_t sB0 = sA0 + SLABB;
    const uint32_t rowStep = 32 * PITCH * 2;
    const __nv_bfloat16* gA0 = g_Yb + (size_t)(split * KSPLIT + lrowg) * D_TOT + a * TILE + lv;
    const __nv_bfloat16* gB0 = g_Yb + (size_t)(split * KSPLIT + lrowg) * D_TOT + b2 * TILE + lv;
    const size_t gRow = (size_t)32 * D_TOT;
    const size_t gChunk = (size_t)CHUNK * D_TOT;

    auto load_chunk = [&](int s, int c) {
        uint32_t so = (uint32_t)(s * 2 * SLABB);
        const __nv_bfloat16* ga = gA0 + c * gChunk;
        const __nv_bfloat16* gb = gB0 + c * gChunk;
        cp16(sA0 + so,           ga);
        cp16(sA0 + so + rowStep, ga + gRow);
        cp16(sB0 + so,           gb);
        cp16(sB0 + so + rowStep, gb + gRow);
    };

    // ---- warp tiling: 2x2 quadrants x 2 k-halves ----
    int wq = wid & 3, kh = wid >> 2;
    int m0 = (wq & 1) * 32;
    int n0 = (wq >> 1) * 32;
    int lrow = (lane & 7) + ((lane >> 4) & 1) * 8;
    int lcol = ((lane >> 3) & 1) * 8;
    uint32_t base = smem_u32(dyn);
    uint32_t aA = base + (uint32_t)((kh * 32 + lrow) * PITCH + m0 + lcol) * 2;
    uint32_t aB = base + SLABB + (uint32_t)((kh * 32 + lrow) * PITCH + n0 + lcol) * 2;
    const uint32_t kStep = 16 * PITCH * 2;

    float acc[2][4][4] = {};

    load_chunk(0, 0);
    asm volatile("cp.async.commit_group;" ::: "memory");
    load_chunk(1, 1);
    asm volatile("cp.async.commit_group;" ::: "memory");

    int s = 0;
    for (int c = 0; c < NCHUNK_S; c++) {
        asm volatile("cp.async.wait_group 1;" ::: "memory");
        __syncthreads();

        if (c + 2 < NCHUNK_S) {
            int s2 = s + 2; if (s2 >= STAGES) s2 -= STAGES;
            load_chunk(s2, c + 2);
        }
        asm volatile("cp.async.commit_group;" ::: "memory");

        uint32_t so = (uint32_t)(s * 2 * SLABB);
        uint32_t af[2][2][4], bf[2][2][4];
        #pragma unroll
        for (int ks = 0; ks < 2; ks++) {
            uint32_t ko = so + ks * kStep;
            ldsm_x4_t(af[ks][0], aA + ko);
            ldsm_x4_t(af[ks][1], aA + ko + 32);
            ldsm_x4_t(bf[ks][0], aB + ko);
            ldsm_x4_t(bf[ks][1], aB + ko + 32);
        }
        #pragma unroll
        for (int ks = 0; ks < 2; ks++)
            #pragma unroll
            for (int mi = 0; mi < 2; mi++) {
                mma_bf16(acc[mi][0], af[ks][mi], bf[ks][0][0], bf[ks][0][2]);
                mma_bf16(acc[mi][1], af[ks][mi], bf[ks][0][1], bf[ks][0][3]);
                mma_bf16(acc[mi][2], af[ks][mi], bf[ks][1][0], bf[ks][1][2]);
                mma_bf16(acc[mi][3], af[ks][mi], bf[ks][1][1], bf[ks][1][3]);
            }
        if (++s >= STAGES) s -= STAGES;
    }

    // ---- merge k-halves via SMEM, write partial Gram ----
    __syncthreads();
    float4* M4 = (float4*)dyn;
    int tt = wq * 32 + lane;
    if (kh == 1) {
        #pragma unroll
        for (int mi = 0; mi < 2; mi++)
            #pragma unroll
            for (int ni = 0; ni < 4; ni++)
                M4[(mi * 4 + ni) * 128 + tt] =
                    make_float4(acc[mi][ni][0], acc[mi][ni][1],
                                acc[mi][ni][2], acc[mi][ni][3]);
    }
    __syncthreads();
    if (kh == 0) {
        float4* G4 = (float4*)g_G + ((size_t)(split * NTILES + blk)) * 1024;
        #pragma unroll
        for (int mi = 0; mi < 2; mi++)
            #pragma unroll
            for (int ni = 0; ni < 4; ni++) {
                int f = mi * 4 + ni;
                float4 v = M4[f * 128 + tt];
                G4[f * 128 + tt] = make_float4(acc[mi][ni][0] + v.x,
                                               acc[mi][ni][1] + v.y,
                                               acc[mi][ni][2] + v.z,
                                               acc[mi][ni][3] + v.w);
            }
    }

    // ---- decoupled per-tile combine (threadFenceReduction pattern) ----
    __syncthreads();
    if (t == 0) {
        __threadfence();
        s_comb = (atomicAdd(&g_tile_count[blk], 1u) == NSPLIT - 1);
    }
    __syncthreads();
    if (!s_comb) return;

    __threadfence();   // acquire partials written by sibling CTAs
    {
        const float4* G4 = (const float4*)g_G;
        float sum = 0.f;
        #pragma unroll
        for (int f = 0; f < 4; f++) {
            size_t idx = (size_t)blk * 1024 + f * 256 + t;
            float x = 0.f, y = 0.f, z = 0.f, w = 0.f;
            #pragma unroll
            for (int sp = 0; sp < NSPLIT; sp++) {   // fixed order: deterministic
                float4 u = G4[(size_t)sp * NTILES * 1024 + idx];
                x += u.x; y += u.y; z += u.z; w += u.w;
            }
            sum += x * x + y * y + z * z + w * w;
        }
        #pragma unroll
        for (int o = 16; o > 0; o >>= 1)
            sum += __shfl_xor_sync(0xFFFFFFFFu, sum, o);
        if (lane == 0) sred[wid] = sum;
    }
    __syncthreads();
    if (t == 0) {
        float tot = 0.f;
        #pragma unroll
        for (int i = 0; i < 8; i++) tot += sred[i];
        float sp = ((a < 2) != (b2 < 2)) ? -1.f : 1.f;
        float w  = sp * ((a == b2) ? 1.f : 2.f);
        g_part[blk] = w * tot;
        g_tile_count[blk] = 0;     // reset for next graph replay
        __threadfence();
        s_last = (atomicAdd(&g_count, 1u) == NTILES - 1);
    }
    __syncthreads();

    // ---- global finalize by last tile-combiner ----
    if (s_last) {
        __threadfence();
        __shared__ float fs[256];
        fs[t] = (t < NTILES) ? g_part[t] : 0.f;
        __syncthreads();
        #pragma unroll
        for (int o = 128; o > 0; o >>= 1) {
            if (t < o) fs[t] += fs[t + o];
            __syncthreads();
        }
        if (t == 0) {
            out[0] = fs[0] / ((float)N_SAMPLES * (float)(N_SAMPLES - 1));
            g_count = 0;           // reset for next graph replay
        }
    }
}

// ---------------------------------------------------------------------------
extern "C" void kernel_launch(void* const* d_in, const int* in_sizes, int n_in,
                              void* d_out, int out_size) {
    const float* red;
    const float* full;
    if (in_sizes[0] == N_SAMPLES * D_RED) {
        red  = (const float*)d_in[0];
        full = (const float*)d_in[1];
    } else {
        red  = (const float*)d_in[1];
        full = (const float*)d_in[0];
    }

    static int attr_done = 0;
    if (!attr_done) {
        cudaFuncSetAttribute(gram_kernel, cudaFuncAttributeMaxDynamicSharedMemorySize,
                             GSMEM);
        attr_done = 1;
    }

    normalize_kernel<<<N_SAMPLES / 8, 256>>>(red, full);
    gram_kernel<<<dim3(NTILES, NSPLIT), 256, GSMEM>>>((float*)d_out);
}